// round 8
// baseline (speedup 1.0000x reference)
#include <cuda_runtime.h>
#include <math.h>

typedef unsigned long long ull;

#define BATCH  128
#define TSTEPS 256
#define NBLK   128

// ---------------- device scratch (no runtime allocation allowed) -----------
__device__ float g_P[2][1024][4096];           // emb @ W_ih(layer0)^T per dir
__device__ float g_h[2][2][2][BATCH * 1024];   // [layer][dir][buf][b*H+j]
__device__ float g_c[2][2][BATCH * 1024];      // [layer][dir]
__device__ float g_wh[BATCH * 2048];           // scrambled fc input (dense)
__device__ float g_logits[2][BATCH * 1024];    // split-K partials
__device__ int   g_feed[BATCH];
__device__ int   g_ended[BATCH];
__device__ unsigned g_cnt = 0;                 // grid barrier state
__device__ unsigned g_gen = 0;

// ---------------- shared memory layout (45568 B < 48K static limit) --------
struct Smem {
    float As[16][132];   // 8448 B
    float Bs[16][68];    // 4352 B
    float zs[128][64];   // 32768 B (also scratch for final phase)
};

// ---------------- f32x2 packed FMA helpers ---------------------------------
__device__ __forceinline__ ull pk2(float lo, float hi) {
    ull r; asm("mov.b64 %0, {%1,%2};" : "=l"(r) : "f"(lo), "f"(hi)); return r;
}
__device__ __forceinline__ void fma2(ull& d, ull a, ull b) {
    asm("fma.rn.f32x2 %0, %1, %2, %0;" : "+l"(d) : "l"(a), "l"(b));
}
__device__ __forceinline__ float2 unpk(ull v) {
    float2 r; asm("mov.b64 {%0,%1}, %2;" : "=f"(r.x), "=f"(r.y) : "l"(v)); return r;
}
__device__ __forceinline__ float sigf(float x) { return 1.0f / (1.0f + expf(-x)); }

// ---------------- software grid barrier (all NBLK blocks co-resident) ------
__device__ __forceinline__ void gbar() {
    __threadfence();              // every thread publishes its global writes
    __syncthreads();
    if (threadIdx.x == 0) {
        unsigned gen = atomicAdd(&g_gen, 0u);        // read before arriving
        unsigned arrived = atomicAdd(&g_cnt, 1u);
        if (arrived == NBLK - 1u) {
            atomicExch(&g_cnt, 0u);
            __threadfence();
            atomicAdd(&g_gen, 1u);                   // release
        } else {
            while (atomicAdd(&g_gen, 0u) == gen) { __nanosleep(64); }
        }
        __threadfence();                             // acquire
    }
    __syncthreads();
}

// ---------------- init ------------------------------------------------------
__global__ void init_kernel(const int* __restrict__ yy,
                            const float* __restrict__ h_t,
                            const float* __restrict__ h_tr,
                            const float* __restrict__ c0,
                            const float* __restrict__ c0r) {
    int i = blockIdx.x * blockDim.x + threadIdx.x;
    const int LBH = BATCH * 1024;
    if (i < 2 * LBH) {
        int l = i / LBH;
        int r = i % LBH;
        int j = r & 1023;
        g_h[l][0][0][r] = h_t[l * LBH + r];
        g_h[l][1][0][r] = h_tr[l * LBH + r];
        g_c[l][0][r] = c0[l * 1024 + j];
        g_c[l][1][r] = c0r[l * 1024 + j];
    }
    if (i < BATCH) {
        g_feed[i] = yy[i * TSTEPS];   // yy_pad[b, 0]
        g_ended[i] = 0;
    }
}

// ---------------- P precompute: M=1024,N=4096,K=1024 per dir ---------------
__global__ void __launch_bounds__(256) pcomp_kernel(
    const float* __restrict__ emb,
    const float* __restrict__ W_ih, const float* __restrict__ W_ihr) {
    const int dir = blockIdx.z;
    const float* Bw = dir ? W_ihr : W_ih;   // layer-0 block of W_ih
    const int n0g = blockIdx.x << 6;
    const int m0g = blockIdx.y << 7;
    const int tid = threadIdx.x;
    const int ty = tid >> 4, tx = tid & 15;
    const int m0 = ty << 3, n0 = tx << 2;
    const int r = tid >> 2, q4 = (tid & 3) << 2;

    __shared__ float As[16][132];
    __shared__ float Bs[16][68];

    ull acc[4][4];
#pragma unroll
    for (int i = 0; i < 4; i++)
#pragma unroll
        for (int j = 0; j < 4; j++) acc[i][j] = 0ULL;

    const float* arow0 = emb + (size_t)(m0g + r) * 1024 + q4;
    const float* arow1 = emb + (size_t)(m0g + r + 64) * 1024 + q4;
    const float* brow  = Bw + (size_t)(n0g + r) * 1024 + q4;

    float4 pa0 = __ldg((const float4*)arow0);
    float4 pa1 = __ldg((const float4*)arow1);
    float4 pb  = __ldg((const float4*)brow);

    for (int k0 = 0; k0 < 1024; k0 += 16) {
        __syncthreads();
        As[q4 + 0][r] = pa0.x; As[q4 + 1][r] = pa0.y; As[q4 + 2][r] = pa0.z; As[q4 + 3][r] = pa0.w;
        As[q4 + 0][r + 64] = pa1.x; As[q4 + 1][r + 64] = pa1.y; As[q4 + 2][r + 64] = pa1.z; As[q4 + 3][r + 64] = pa1.w;
        Bs[q4 + 0][r] = pb.x; Bs[q4 + 1][r] = pb.y; Bs[q4 + 2][r] = pb.z; Bs[q4 + 3][r] = pb.w;
        __syncthreads();
        if (k0 + 16 < 1024) {
            pa0 = __ldg((const float4*)(arow0 + k0 + 16));
            pa1 = __ldg((const float4*)(arow1 + k0 + 16));
            pb  = __ldg((const float4*)(brow + k0 + 16));
        }
#pragma unroll
        for (int k = 0; k < 16; k++) {
            const ull* ap = (const ull*)&As[k][m0];
            ull a0 = ap[0], a1 = ap[1], a2 = ap[2], a3 = ap[3];
            float4 bv = *(const float4*)&Bs[k][n0];
            ull p0 = pk2(bv.x, bv.x), p1 = pk2(bv.y, bv.y);
            ull p2 = pk2(bv.z, bv.z), p3 = pk2(bv.w, bv.w);
            fma2(acc[0][0], a0, p0); fma2(acc[0][1], a0, p1); fma2(acc[0][2], a0, p2); fma2(acc[0][3], a0, p3);
            fma2(acc[1][0], a1, p0); fma2(acc[1][1], a1, p1); fma2(acc[1][2], a1, p2); fma2(acc[1][3], a1, p3);
            fma2(acc[2][0], a2, p0); fma2(acc[2][1], a2, p1); fma2(acc[2][2], a2, p2); fma2(acc[2][3], a2, p3);
            fma2(acc[3][0], a3, p0); fma2(acc[3][1], a3, p1); fma2(acc[3][2], a3, p2); fma2(acc[3][3], a3, p3);
        }
    }
#pragma unroll
    for (int mp = 0; mp < 4; mp++) {
        int m = m0g + m0 + (mp << 1);
#pragma unroll
        for (int j = 0; j < 4; j++) {
            float2 v = unpk(acc[mp][j]);
            g_P[dir][m][n0g + n0 + j] = v.x;
            g_P[dir][m + 1][n0g + n0 + j] = v.y;
        }
    }
}

// ---------------- fused LSTM cell phase (inside persistent kernel) ---------
// layer 0: z = P[feed] + h0_prev @ Whh0^T + biases
// layer 1: z = h0_new @ Wih1^T + h1_prev @ Whh1^T + biases
// block (jt = bid&63, dir = bid>>6) computes 4 gates x 16 j; gate math + c/h
// update fused in epilogue; layer 1 scatters h into g_wh.
__device__ __forceinline__ void cell_phase(Smem& sm, int layer, int p, int bid,
    const float* __restrict__ W_ih, const float* __restrict__ W_hh,
    const float* __restrict__ b_ih, const float* __restrict__ b_hh,
    const float* __restrict__ W_ihr, const float* __restrict__ W_hhr,
    const float* __restrict__ b_ihr, const float* __restrict__ b_hhr) {
    const int dir = bid >> 6;
    const int j0 = (bid & 63) << 4;
    const int np = p ^ 1;
    const int tid = threadIdx.x;
    const int ty = tid >> 4, tx = tid & 15;
    const int m0 = ty << 3, n0 = tx << 2;
    const int r = tid >> 2, q4 = (tid & 3) << 2;

    const float* Wih = (dir ? W_ihr : W_ih) + (size_t)layer * (4096 * 1024);
    const float* Whh = (dir ? W_hhr : W_hh) + (size_t)layer * (4096 * 1024);
    const float* bi = (dir ? b_ihr : b_ih) + layer * 4096;
    const float* bh = (dir ? b_hhr : b_hh) + layer * 4096;

    const float* segA[2];
    const float* segB[2];
    int nseg;
    if (layer == 0) {
        segA[0] = g_h[0][dir][p]; segB[0] = Whh; nseg = 1;
        segA[1] = segA[0];        segB[1] = segB[0];
    } else {
        segA[0] = g_h[0][dir][np]; segB[0] = Wih;   // h0 produced this step
        segA[1] = g_h[1][dir][p];  segB[1] = Whh;   // h1 from previous step
        nseg = 2;
    }

    const int wrow = ((r >> 4) << 10) + j0 + (r & 15);  // gate*1024 + j0 + jj

    ull acc[4][4];
#pragma unroll
    for (int i = 0; i < 4; i++)
#pragma unroll
        for (int j = 0; j < 4; j++) acc[i][j] = 0ULL;

    // register-staged prefetch (A = shared state -> L2-only loads)
    float4 pa0 = __ldcg((const float4*)(segA[0] + (size_t)r * 1024 + q4));
    float4 pa1 = __ldcg((const float4*)(segA[0] + (size_t)(r + 64) * 1024 + q4));
    float4 pb  = __ldg ((const float4*)(segB[0] + (size_t)wrow * 1024 + q4));

    const int total = nseg << 6;
    for (int kk = 0; kk < total; ++kk) {
        __syncthreads();
        sm.As[q4 + 0][r] = pa0.x; sm.As[q4 + 1][r] = pa0.y;
        sm.As[q4 + 2][r] = pa0.z; sm.As[q4 + 3][r] = pa0.w;
        sm.As[q4 + 0][r + 64] = pa1.x; sm.As[q4 + 1][r + 64] = pa1.y;
        sm.As[q4 + 2][r + 64] = pa1.z; sm.As[q4 + 3][r + 64] = pa1.w;
        sm.Bs[q4 + 0][r] = pb.x; sm.Bs[q4 + 1][r] = pb.y;
        sm.Bs[q4 + 2][r] = pb.z; sm.Bs[q4 + 3][r] = pb.w;
        __syncthreads();
        if (kk + 1 < total) {
            int s = (kk + 1) >> 6;
            int k0 = ((kk + 1) & 63) << 4;
            pa0 = __ldcg((const float4*)(segA[s] + (size_t)r * 1024 + k0 + q4));
            pa1 = __ldcg((const float4*)(segA[s] + (size_t)(r + 64) * 1024 + k0 + q4));
            pb  = __ldg ((const float4*)(segB[s] + (size_t)wrow * 1024 + k0 + q4));
        }
#pragma unroll
        for (int k = 0; k < 16; k++) {
            const ull* ap = (const ull*)&sm.As[k][m0];
            ull a0 = ap[0], a1 = ap[1], a2 = ap[2], a3 = ap[3];
            float4 bv = *(const float4*)&sm.Bs[k][n0];
            ull p0 = pk2(bv.x, bv.x), p1 = pk2(bv.y, bv.y);
            ull p2 = pk2(bv.z, bv.z), p3 = pk2(bv.w, bv.w);
            fma2(acc[0][0], a0, p0); fma2(acc[0][1], a0, p1); fma2(acc[0][2], a0, p2); fma2(acc[0][3], a0, p3);
            fma2(acc[1][0], a1, p0); fma2(acc[1][1], a1, p1); fma2(acc[1][2], a1, p2); fma2(acc[1][3], a1, p3);
            fma2(acc[2][0], a2, p0); fma2(acc[2][1], a2, p1); fma2(acc[2][2], a2, p2); fma2(acc[2][3], a2, p3);
            fma2(acc[3][0], a3, p0); fma2(acc[3][1], a3, p1); fma2(acc[3][2], a3, p2); fma2(acc[3][3], a3, p3);
        }
    }

    // dump accumulators so each thread can gather all 4 gates of one (b, j)
    __syncthreads();
#pragma unroll
    for (int mp = 0; mp < 4; mp++) {
#pragma unroll
        for (int j = 0; j < 4; j++) {
            float2 v = unpk(acc[mp][j]);
            sm.zs[m0 + (mp << 1)][n0 + j] = v.x;
            sm.zs[m0 + (mp << 1) + 1][n0 + j] = v.y;
        }
    }
    __syncthreads();

    // fused gate epilogue: 2048 (b, jj) pairs over 256 threads
#pragma unroll
    for (int it = 0; it < 8; ++it) {
        int pidx = tid + (it << 8);
        int b = pidx >> 4, jj = pidx & 15;
        int jg = j0 + jj;
        float zi = sm.zs[b][jj]      + bi[jg]        + bh[jg];
        float zf = sm.zs[b][16 + jj] + bi[1024 + jg] + bh[1024 + jg];
        float zg = sm.zs[b][32 + jj] + bi[2048 + jg] + bh[2048 + jg];
        float zo = sm.zs[b][48 + jj] + bi[3072 + jg] + bh[3072 + jg];
        if (layer == 0) {
            int feed = __ldcg(&g_feed[b]);
            const float* pr = g_P[dir][feed];
            zi += pr[jg]; zf += pr[1024 + jg]; zg += pr[2048 + jg]; zo += pr[3072 + jg];
        }
        float ig = sigf(zi), fg = sigf(zf), gv = tanhf(zg), og = sigf(zo);
        int idx = b * 1024 + jg;
        float cnew = fg * g_c[layer][dir][idx] + ig * gv;  // c is block-private
        float hnew = og * tanhf(cnew);
        g_c[layer][dir][idx] = cnew;
        g_h[layer][dir][np][idx] = hnew;
        if (layer == 1) {
            // wh[b'][j'] = concat[j'%128, b'*16 + j'/128]; inverse scatter:
            int cc = (dir << 10) + jg;
            g_wh[((cc >> 4) << 11) + ((cc & 15) << 7) + b] = hnew;
        }
    }
}

// ---------------- fc phase: split-K=2 deterministic partials ----------------
__device__ __forceinline__ void fc_phase(Smem& sm, int bid, const float* __restrict__ fcW) {
    const int ks = bid >> 6;
    const int n0g = (bid & 63) << 4;
    const int koff = ks << 10;
    const int tid = threadIdx.x;
    const int ty = tid >> 4, tx = tid & 15;
    const int m0 = ty << 3;
    const int r = tid >> 2, q4 = (tid & 3) << 2;
    const bool bload = (tid < 64);

    ull acc[4] = {0ULL, 0ULL, 0ULL, 0ULL};

    float4 pa0 = __ldcg((const float4*)(g_wh + (size_t)r * 2048 + koff + q4));
    float4 pa1 = __ldcg((const float4*)(g_wh + (size_t)(r + 64) * 2048 + koff + q4));
    float4 pb = make_float4(0.f, 0.f, 0.f, 0.f);
    if (bload) pb = __ldg((const float4*)(fcW + (size_t)(n0g + r) * 2048 + koff + q4));

    for (int k0 = 0; k0 < 1024; k0 += 16) {
        __syncthreads();
        sm.As[q4 + 0][r] = pa0.x; sm.As[q4 + 1][r] = pa0.y;
        sm.As[q4 + 2][r] = pa0.z; sm.As[q4 + 3][r] = pa0.w;
        sm.As[q4 + 0][r + 64] = pa1.x; sm.As[q4 + 1][r + 64] = pa1.y;
        sm.As[q4 + 2][r + 64] = pa1.z; sm.As[q4 + 3][r + 64] = pa1.w;
        if (bload) {
            sm.Bs[q4 + 0][r] = pb.x; sm.Bs[q4 + 1][r] = pb.y;
            sm.Bs[q4 + 2][r] = pb.z; sm.Bs[q4 + 3][r] = pb.w;
        }
        __syncthreads();
        if (k0 + 16 < 1024) {
            pa0 = __ldcg((const float4*)(g_wh + (size_t)r * 2048 + koff + k0 + 16 + q4));
            pa1 = __ldcg((const float4*)(g_wh + (size_t)(r + 64) * 2048 + koff + k0 + 16 + q4));
            if (bload) pb = __ldg((const float4*)(fcW + (size_t)(n0g + r) * 2048 + koff + k0 + 16 + q4));
        }
#pragma unroll
        for (int k = 0; k < 16; k++) {
            const ull* ap = (const ull*)&sm.As[k][m0];
            float bb = sm.Bs[k][tx];
            ull pbk = pk2(bb, bb);
            fma2(acc[0], ap[0], pbk);
            fma2(acc[1], ap[1], pbk);
            fma2(acc[2], ap[2], pbk);
            fma2(acc[3], ap[3], pbk);
        }
    }

    int e = n0g + tx;
    float* lp = g_logits[ks];
#pragma unroll
    for (int mp = 0; mp < 4; mp++) {
        float2 v = unpk(acc[mp]);
        lp[(m0 + (mp << 1)) * 1024 + e] = v.x;
        lp[(m0 + (mp << 1) + 1) * 1024 + e] = v.y;
    }
}

// ---------------- final phase: reduce, mask, argmax, softmax, feedback ------
__device__ __forceinline__ void final_phase(Smem& sm, int bid,
                                            const float* __restrict__ fc_b,
                                            float* __restrict__ out, int t) {
    const int b = bid;                  // NBLK == BATCH
    const int tid = threadIdx.x;
    float* sl = &sm.zs[0][0];           // 1024 floats
    float* sv = sl + 1024;              // 256
    int*   si = (int*)(sl + 1280);      // 256
    float* ssum = sl + 1536;            // 256

    const int end = __ldcg(&g_ended[b]);
    float bv = -3.402823466e38f;
    int bidx = 0;
    for (int e = tid; e < 1024; e += 256) {
        float v;
        if (end)
            v = (e == 1) ? 1.0f : 0.0f;   // EOS one-hot
        else
            v = __ldcg(&g_logits[0][b * 1024 + e]) + __ldcg(&g_logits[1][b * 1024 + e]) + fc_b[e];
        sl[e] = v;
        if (v > bv) { bv = v; bidx = e; }  // strict > keeps first occurrence
    }
    sv[tid] = bv; si[tid] = bidx;
    __syncthreads();
    for (int s = 128; s > 0; s >>= 1) {
        if (tid < s) {
            float v2 = sv[tid + s]; int i2 = si[tid + s];
            if (v2 > sv[tid] || (v2 == sv[tid] && i2 < si[tid])) { sv[tid] = v2; si[tid] = i2; }
        }
        __syncthreads();
    }
    float mx = sv[0];
    int label = si[0];
    __syncthreads();

    float ps = 0.0f;
    for (int e = tid; e < 1024; e += 256) ps += expf(sl[e] - mx);
    ssum[tid] = ps;
    __syncthreads();
    for (int s = 128; s > 0; s >>= 1) {
        if (tid < s) ssum[tid] += ssum[tid + s];
        __syncthreads();
    }
    float inv = 1.0f / ssum[0];

    float* orow = out + ((size_t)b * TSTEPS + t) * 1024;
    for (int e = tid; e < 1024; e += 256) orow[e] = expf(sl[e] - mx) * inv;

    if (tid == 0) {
        g_feed[b] = label;
        g_ended[b] = end | (label == 1);   // EOS = 1
    }
}

// ---------------- persistent main kernel: whole 256-step loop ---------------
__global__ void __launch_bounds__(256, 1) main_kernel(
    const float* __restrict__ W_ih, const float* __restrict__ W_hh,
    const float* __restrict__ b_ih, const float* __restrict__ b_hh,
    const float* __restrict__ W_ihr, const float* __restrict__ W_hhr,
    const float* __restrict__ b_ihr, const float* __restrict__ b_hhr,
    const float* __restrict__ fcW, const float* __restrict__ fc_b,
    float* __restrict__ out) {
    __shared__ Smem sm;
    const int bid = blockIdx.x;

    for (int t = 0; t < TSTEPS; ++t) {
        const int p = t & 1;
        for (int layer = 0; layer < 2; ++layer) {
            cell_phase(sm, layer, p, bid, W_ih, W_hh, b_ih, b_hh,
                       W_ihr, W_hhr, b_ihr, b_hhr);
            gbar();
        }
        fc_phase(sm, bid, fcW);
        gbar();
        final_phase(sm, bid, fc_b, out, t);
        gbar();
    }
}

// ---------------- launch: 3 graph nodes total --------------------------------
extern "C" void kernel_launch(void* const* d_in, const int* in_sizes, int n_in,
                              void* d_out, int out_size) {
    const int* yy = (const int*)d_in[0];
    const float* h_t = (const float*)d_in[1];
    const float* h_tr = (const float*)d_in[2];
    // d_in[3] = x_lens (unused by the reference computation)
    const float* emb = (const float*)d_in[4];
    const float* W_ih = (const float*)d_in[5];
    const float* W_hh = (const float*)d_in[6];
    const float* b_ih = (const float*)d_in[7];
    const float* b_hh = (const float*)d_in[8];
    const float* W_ihr = (const float*)d_in[9];
    const float* W_hhr = (const float*)d_in[10];
    const float* b_ihr = (const float*)d_in[11];
    const float* b_hhr = (const float*)d_in[12];
    const float* c0 = (const float*)d_in[13];
    const float* c0r = (const float*)d_in[14];
    const float* fc_W = (const float*)d_in[15];
    const float* fc_b = (const float*)d_in[16];
    float* out = (float*)d_out;

    init_kernel<<<1024, 256>>>(yy, h_t, h_tr, c0, c0r);
    pcomp_kernel<<<dim3(64, 8, 2), 256>>>(emb, W_ih, W_ihr);
    main_kernel<<<NBLK, 256>>>(W_ih, W_hh, b_ih, b_hh,
                               W_ihr, W_hhr, b_ihr, b_hhr,
                               fc_W, fc_b, out);
}

// round 9
// speedup vs baseline: 1.0024x; 1.0024x over previous
#include <cuda_runtime.h>
#include <math.h>

typedef unsigned long long ull;

#define BATCH  128
#define TSTEPS 256
#define NBLK   128

// ---------------- device scratch (no runtime allocation allowed) -----------
__device__ float g_P[2][1024][4096];           // emb @ W_ih(layer0)^T per dir
__device__ float g_h[2][2][2][BATCH * 1024];   // [layer][dir][buf][b*H+j]
__device__ float g_c[2][2][BATCH * 1024];      // [layer][dir]
__device__ float g_wh[BATCH * 2048];           // scrambled fc input (dense)
__device__ float g_logits[2][BATCH * 1024];    // split-K partials
__device__ int   g_feed[BATCH];
__device__ int   g_ended[BATCH];
__device__ unsigned g_cnt = 0;                 // grid barrier state
__device__ unsigned g_gen = 0;

// ---------------- shared: union of GEMM double-buffers and epilogue scratch
struct GemmBufs {                // 25600 B
    float As[2][16][132];
    float Bs[2][16][68];
};
#define SRAW_BYTES 32768         // 128*64 floats for zs / final scratch

// ---------------- f32x2 packed FMA helpers ---------------------------------
__device__ __forceinline__ ull pk2(float lo, float hi) {
    ull r; asm("mov.b64 %0, {%1,%2};" : "=l"(r) : "f"(lo), "f"(hi)); return r;
}
__device__ __forceinline__ void fma2(ull& d, ull a, ull b) {
    asm("fma.rn.f32x2 %0, %1, %2, %0;" : "+l"(d) : "l"(a), "l"(b));
}
__device__ __forceinline__ float2 unpk(ull v) {
    float2 r; asm("mov.b64 {%0,%1}, %2;" : "=f"(r.x), "=f"(r.y) : "l"(v)); return r;
}
__device__ __forceinline__ float sigf(float x) { return 1.0f / (1.0f + expf(-x)); }

// ---------------- software grid barrier (all NBLK blocks co-resident) ------
__device__ __forceinline__ void gbar() {
    __threadfence();
    __syncthreads();
    if (threadIdx.x == 0) {
        unsigned gen = atomicAdd(&g_gen, 0u);
        unsigned arrived = atomicAdd(&g_cnt, 1u);
        if (arrived == NBLK - 1u) {
            atomicExch(&g_cnt, 0u);
            __threadfence();
            atomicAdd(&g_gen, 1u);
        } else {
            while (atomicAdd(&g_gen, 0u) == gen) { __nanosleep(64); }
        }
        __threadfence();
    }
    __syncthreads();
}

// ---------------- shared-tile store (A: 128x16, B: 64x16) ------------------
__device__ __forceinline__ void sts_tile(float (*As)[132], float (*Bs)[68],
                                         int r, int q4,
                                         const float4& pa0, const float4& pa1,
                                         const float4& pb) {
    As[q4 + 0][r] = pa0.x; As[q4 + 1][r] = pa0.y;
    As[q4 + 2][r] = pa0.z; As[q4 + 3][r] = pa0.w;
    As[q4 + 0][r + 64] = pa1.x; As[q4 + 1][r + 64] = pa1.y;
    As[q4 + 2][r + 64] = pa1.z; As[q4 + 3][r + 64] = pa1.w;
    Bs[q4 + 0][r] = pb.x; Bs[q4 + 1][r] = pb.y;
    Bs[q4 + 2][r] = pb.z; Bs[q4 + 3][r] = pb.w;
}

// ---------------- 16-k microkernel: 8m x 4n per thread via f32x2 -----------
__device__ __forceinline__ void mma16(const float (*As)[132], const float (*Bs)[68],
                                      int m0, int n0, ull acc[4][4]) {
#pragma unroll
    for (int k = 0; k < 16; k++) {
        const ull* ap = (const ull*)&As[k][m0];
        ull a0 = ap[0], a1 = ap[1], a2 = ap[2], a3 = ap[3];
        float4 bv = *(const float4*)&Bs[k][n0];
        ull p0 = pk2(bv.x, bv.x), p1 = pk2(bv.y, bv.y);
        ull p2 = pk2(bv.z, bv.z), p3 = pk2(bv.w, bv.w);
        fma2(acc[0][0], a0, p0); fma2(acc[0][1], a0, p1); fma2(acc[0][2], a0, p2); fma2(acc[0][3], a0, p3);
        fma2(acc[1][0], a1, p0); fma2(acc[1][1], a1, p1); fma2(acc[1][2], a1, p2); fma2(acc[1][3], a1, p3);
        fma2(acc[2][0], a2, p0); fma2(acc[2][1], a2, p1); fma2(acc[2][2], a2, p2); fma2(acc[2][3], a2, p3);
        fma2(acc[3][0], a3, p0); fma2(acc[3][1], a3, p1); fma2(acc[3][2], a3, p2); fma2(acc[3][3], a3, p3);
    }
}

// ---------------- init phase -------------------------------------------------
__device__ __forceinline__ void init_phase(int bid, const int* __restrict__ yy,
                                           const float* __restrict__ h_t,
                                           const float* __restrict__ h_tr,
                                           const float* __restrict__ c0,
                                           const float* __restrict__ c0r) {
    const int tid = threadIdx.x;
    const int LBH = BATCH * 1024;
    for (int i = bid * 256 + tid; i < 2 * LBH; i += NBLK * 256) {
        int l = i / LBH;
        int r = i % LBH;
        int j = r & 1023;
        g_h[l][0][0][r] = h_t[l * LBH + r];
        g_h[l][1][0][r] = h_tr[l * LBH + r];
        g_c[l][0][r] = c0[l * 1024 + j];
        g_c[l][1][r] = c0r[l * 1024 + j];
    }
    if (bid == 0 && tid < BATCH) {
        g_feed[tid] = yy[tid * TSTEPS];   // yy_pad[b, 0]
        g_ended[tid] = 0;
    }
}

// ---------------- pcomp phase: P[dir][m][n] = emb @ W_ih(l0)^T --------------
// 1024 tiles (dir 2 x mt 8 x nt 64) of (128m x 64n, K=1024); 8 tiles/block.
__device__ __forceinline__ void pcomp_phase(GemmBufs& g, int bid,
                                            const float* __restrict__ emb,
                                            const float* __restrict__ W_ih,
                                            const float* __restrict__ W_ihr) {
    const int tid = threadIdx.x;
    const int ty = tid >> 4, tx = tid & 15;
    const int m0 = ty << 3, n0 = tx << 2;
    const int r = tid >> 2, q4 = (tid & 3) << 2;

    for (int it = 0; it < 8; ++it) {
        int tile = bid + (it << 7);           // 0..1023
        int dir = tile >> 9;
        int mt = (tile >> 6) & 7;
        int nt = tile & 63;
        const float* Bw = dir ? W_ihr : W_ih;
        const int m0g = mt << 7, n0g = nt << 6;

        const float* arow0 = emb + (size_t)(m0g + r) * 1024 + q4;
        const float* arow1 = emb + (size_t)(m0g + r + 64) * 1024 + q4;
        const float* brow  = Bw + (size_t)(n0g + r) * 1024 + q4;

        ull acc[4][4];
#pragma unroll
        for (int i = 0; i < 4; i++)
#pragma unroll
            for (int j = 0; j < 4; j++) acc[i][j] = 0ULL;

        float4 pa0 = __ldg((const float4*)arow0);
        float4 pa1 = __ldg((const float4*)arow1);
        float4 pb  = __ldg((const float4*)brow);
        sts_tile(g.As[0], g.Bs[0], r, q4, pa0, pa1, pb);
        __syncthreads();
        int cur = 0;
        for (int kk = 0; kk < 64; ++kk) {
            const bool more = (kk + 1) < 64;
            if (more) {
                int k0 = (kk + 1) << 4;
                pa0 = __ldg((const float4*)(arow0 + k0));
                pa1 = __ldg((const float4*)(arow1 + k0));
                pb  = __ldg((const float4*)(brow + k0));
            }
            mma16(g.As[cur], g.Bs[cur], m0, n0, acc);
            if (more) {
                sts_tile(g.As[cur ^ 1], g.Bs[cur ^ 1], r, q4, pa0, pa1, pb);
                __syncthreads();
                cur ^= 1;
            }
        }
        __syncthreads();
#pragma unroll
        for (int mp = 0; mp < 4; mp++) {
            int m = m0g + m0 + (mp << 1);
#pragma unroll
            for (int j = 0; j < 4; j++) {
                float2 v = unpk(acc[mp][j]);
                g_P[dir][m][n0g + n0 + j] = v.x;
                g_P[dir][m + 1][n0g + n0 + j] = v.y;
            }
        }
        __syncthreads();
    }
}

// ---------------- fused LSTM cell phase -------------------------------------
// layer 0: z = P[feed] + h0_prev @ Whh0^T + biases
// layer 1: z = h0_new @ Wih1^T + h1_prev @ Whh1^T + biases
__device__ __forceinline__ void cell_phase(GemmBufs& g, float (*zs)[64],
    int layer, int p, int bid,
    const float* __restrict__ W_ih, const float* __restrict__ W_hh,
    const float* __restrict__ b_ih, const float* __restrict__ b_hh,
    const float* __restrict__ W_ihr, const float* __restrict__ W_hhr,
    const float* __restrict__ b_ihr, const float* __restrict__ b_hhr) {
    const int dir = bid >> 6;
    const int j0 = (bid & 63) << 4;
    const int np = p ^ 1;
    const int tid = threadIdx.x;
    const int ty = tid >> 4, tx = tid & 15;
    const int m0 = ty << 3, n0 = tx << 2;
    const int r = tid >> 2, q4 = (tid & 3) << 2;

    const float* Wih = (dir ? W_ihr : W_ih) + (size_t)layer * (4096 * 1024);
    const float* Whh = (dir ? W_hhr : W_hh) + (size_t)layer * (4096 * 1024);
    const float* bi = (dir ? b_ihr : b_ih) + layer * 4096;
    const float* bh = (dir ? b_hhr : b_hh) + layer * 4096;

    const float* segA[2];
    const float* segB[2];
    int nseg;
    if (layer == 0) {
        segA[0] = g_h[0][dir][p]; segB[0] = Whh; nseg = 1;
        segA[1] = segA[0];        segB[1] = segB[0];
    } else {
        segA[0] = g_h[0][dir][np]; segB[0] = Wih;   // h0 produced this step
        segA[1] = g_h[1][dir][p];  segB[1] = Whh;   // h1 from previous step
        nseg = 2;
    }

    const int wrow = ((r >> 4) << 10) + j0 + (r & 15);  // gate*1024 + j0 + jj

    ull acc[4][4];
#pragma unroll
    for (int i = 0; i < 4; i++)
#pragma unroll
        for (int j = 0; j < 4; j++) acc[i][j] = 0ULL;

    float4 pa0 = __ldcg((const float4*)(segA[0] + (size_t)r * 1024 + q4));
    float4 pa1 = __ldcg((const float4*)(segA[0] + (size_t)(r + 64) * 1024 + q4));
    float4 pb  = __ldg ((const float4*)(segB[0] + (size_t)wrow * 1024 + q4));
    sts_tile(g.As[0], g.Bs[0], r, q4, pa0, pa1, pb);
    __syncthreads();

    const int total = nseg << 6;
    int cur = 0;
    for (int kk = 0; kk < total; ++kk) {
        const bool more = (kk + 1) < total;
        if (more) {
            int s = (kk + 1) >> 6;
            int k0 = ((kk + 1) & 63) << 4;
            pa0 = __ldcg((const float4*)(segA[s] + (size_t)r * 1024 + k0 + q4));
            pa1 = __ldcg((const float4*)(segA[s] + (size_t)(r + 64) * 1024 + k0 + q4));
            pb  = __ldg ((const float4*)(segB[s] + (size_t)wrow * 1024 + k0 + q4));
        }
        mma16(g.As[cur], g.Bs[cur], m0, n0, acc);
        if (more) {
            sts_tile(g.As[cur ^ 1], g.Bs[cur ^ 1], r, q4, pa0, pa1, pb);
            __syncthreads();
            cur ^= 1;
        }
    }

    // dump accumulators into zs (overlaps As/Bs memory; readers are done)
    __syncthreads();
#pragma unroll
    for (int mp = 0; mp < 4; mp++) {
#pragma unroll
        for (int j = 0; j < 4; j++) {
            float2 v = unpk(acc[mp][j]);
            zs[m0 + (mp << 1)][n0 + j] = v.x;
            zs[m0 + (mp << 1) + 1][n0 + j] = v.y;
        }
    }
    __syncthreads();

    // fused gate epilogue: 2048 (b, jj) pairs over 256 threads
#pragma unroll
    for (int it = 0; it < 8; ++it) {
        int pidx = tid + (it << 8);
        int b = pidx >> 4, jj = pidx & 15;
        int jg = j0 + jj;
        float zi = zs[b][jj]      + bi[jg]        + bh[jg];
        float zf = zs[b][16 + jj] + bi[1024 + jg] + bh[1024 + jg];
        float zg = zs[b][32 + jj] + bi[2048 + jg] + bh[2048 + jg];
        float zo = zs[b][48 + jj] + bi[3072 + jg] + bh[3072 + jg];
        if (layer == 0) {
            int feed = __ldcg(&g_feed[b]);
            const float* pr = g_P[dir][feed];
            zi += pr[jg]; zf += pr[1024 + jg]; zg += pr[2048 + jg]; zo += pr[3072 + jg];
        }
        float ig = sigf(zi), fg = sigf(zf), gv = tanhf(zg), og = sigf(zo);
        int idx = b * 1024 + jg;
        float cnew = fg * g_c[layer][dir][idx] + ig * gv;  // c is block-private
        float hnew = og * tanhf(cnew);
        g_c[layer][dir][idx] = cnew;
        g_h[layer][dir][np][idx] = hnew;
        if (layer == 1) {
            int cc = (dir << 10) + jg;   // scrambled fc-input scatter
            g_wh[((cc >> 4) << 11) + ((cc & 15) << 7) + b] = hnew;
        }
    }
}

// ---------------- fc phase: split-K=2 deterministic partials ----------------
__device__ __forceinline__ void fc_phase(GemmBufs& g, int bid,
                                         const float* __restrict__ fcW) {
    const int ks = bid >> 6;
    const int n0g = (bid & 63) << 4;
    const int koff = ks << 10;
    const int tid = threadIdx.x;
    const int ty = tid >> 4, tx = tid & 15;
    const int m0 = ty << 3;
    const int r = tid >> 2, q4 = (tid & 3) << 2;
    const bool bload = (tid < 64);

    ull acc[4] = {0ULL, 0ULL, 0ULL, 0ULL};

    const float* abase0 = g_wh + (size_t)r * 2048 + koff + q4;
    const float* abase1 = g_wh + (size_t)(r + 64) * 2048 + koff + q4;
    const float* bbase  = fcW + (size_t)(n0g + r) * 2048 + koff + q4;

    float4 pa0 = __ldcg((const float4*)abase0);
    float4 pa1 = __ldcg((const float4*)abase1);
    float4 pb = make_float4(0.f, 0.f, 0.f, 0.f);
    if (bload) pb = __ldg((const float4*)bbase);
    {
        float (*As)[132] = g.As[0];
        float (*Bs)[68] = g.Bs[0];
        As[q4 + 0][r] = pa0.x; As[q4 + 1][r] = pa0.y; As[q4 + 2][r] = pa0.z; As[q4 + 3][r] = pa0.w;
        As[q4 + 0][r + 64] = pa1.x; As[q4 + 1][r + 64] = pa1.y; As[q4 + 2][r + 64] = pa1.z; As[q4 + 3][r + 64] = pa1.w;
        if (bload) { Bs[q4 + 0][r] = pb.x; Bs[q4 + 1][r] = pb.y; Bs[q4 + 2][r] = pb.z; Bs[q4 + 3][r] = pb.w; }
    }
    __syncthreads();

    int cur = 0;
    for (int kk = 0; kk < 64; ++kk) {
        const bool more = (kk + 1) < 64;
        if (more) {
            int k0 = (kk + 1) << 4;
            pa0 = __ldcg((const float4*)(abase0 + k0));
            pa1 = __ldcg((const float4*)(abase1 + k0));
            if (bload) pb = __ldg((const float4*)(bbase + k0));
        }
        {
            const float (*As)[132] = g.As[cur];
            const float (*Bs)[68] = g.Bs[cur];
#pragma unroll
            for (int k = 0; k < 16; k++) {
                const ull* ap = (const ull*)&As[k][m0];
                float bb = Bs[k][tx];
                ull pbk = pk2(bb, bb);
                fma2(acc[0], ap[0], pbk);
                fma2(acc[1], ap[1], pbk);
                fma2(acc[2], ap[2], pbk);
                fma2(acc[3], ap[3], pbk);
            }
        }
        if (more) {
            float (*As)[132] = g.As[cur ^ 1];
            float (*Bs)[68] = g.Bs[cur ^ 1];
            As[q4 + 0][r] = pa0.x; As[q4 + 1][r] = pa0.y; As[q4 + 2][r] = pa0.z; As[q4 + 3][r] = pa0.w;
            As[q4 + 0][r + 64] = pa1.x; As[q4 + 1][r + 64] = pa1.y; As[q4 + 2][r + 64] = pa1.z; As[q4 + 3][r + 64] = pa1.w;
            if (bload) { Bs[q4 + 0][r] = pb.x; Bs[q4 + 1][r] = pb.y; Bs[q4 + 2][r] = pb.z; Bs[q4 + 3][r] = pb.w; }
            __syncthreads();
            cur ^= 1;
        }
    }

    int e = n0g + tx;
    float* lp = g_logits[ks];
#pragma unroll
    for (int mp = 0; mp < 4; mp++) {
        float2 v = unpk(acc[mp]);
        lp[(m0 + (mp << 1)) * 1024 + e] = v.x;
        lp[(m0 + (mp << 1) + 1) * 1024 + e] = v.y;
    }
}

// ---------------- final phase: reduce, mask, argmax, softmax, feedback ------
__device__ __forceinline__ void final_phase(float* sraw, int bid,
                                            const float* __restrict__ fc_b,
                                            float* __restrict__ out, int t) {
    const int b = bid;                  // NBLK == BATCH
    const int tid = threadIdx.x;
    float* sl = sraw;                   // 1024 floats
    float* sv = sl + 1024;              // 256
    int*   si = (int*)(sl + 1280);      // 256
    float* ssum = sl + 1536;            // 256

    const int end = __ldcg(&g_ended[b]);
    float bv = -3.402823466e38f;
    int bidx = 0;
    for (int e = tid; e < 1024; e += 256) {
        float v;
        if (end)
            v = (e == 1) ? 1.0f : 0.0f;   // EOS one-hot
        else
            v = __ldcg(&g_logits[0][b * 1024 + e]) + __ldcg(&g_logits[1][b * 1024 + e]) + fc_b[e];
        sl[e] = v;
        if (v > bv) { bv = v; bidx = e; }  // strict > keeps first occurrence
    }
    sv[tid] = bv; si[tid] = bidx;
    __syncthreads();
    for (int s = 128; s > 0; s >>= 1) {
        if (tid < s) {
            float v2 = sv[tid + s]; int i2 = si[tid + s];
            if (v2 > sv[tid] || (v2 == sv[tid] && i2 < si[tid])) { sv[tid] = v2; si[tid] = i2; }
        }
        __syncthreads();
    }
    float mx = sv[0];
    int label = si[0];
    __syncthreads();

    float ps = 0.0f;
    for (int e = tid; e < 1024; e += 256) ps += expf(sl[e] - mx);
    ssum[tid] = ps;
    __syncthreads();
    for (int s = 128; s > 0; s >>= 1) {
        if (tid < s) ssum[tid] += ssum[tid + s];
        __syncthreads();
    }
    float inv = 1.0f / ssum[0];

    float* orow = out + ((size_t)b * TSTEPS + t) * 1024;
    for (int e = tid; e < 1024; e += 256) orow[e] = expf(sl[e] - mx) * inv;

    if (tid == 0) {
        g_feed[b] = label;
        g_ended[b] = end | (label == 1);   // EOS = 1
    }
}

// ---------------- mega kernel: init + pcomp + 256 decode steps --------------
__global__ void __launch_bounds__(256, 1) main_kernel(
    const int* __restrict__ yy,
    const float* __restrict__ h_t, const float* __restrict__ h_tr,
    const float* __restrict__ c0, const float* __restrict__ c0r,
    const float* __restrict__ emb,
    const float* __restrict__ W_ih, const float* __restrict__ W_hh,
    const float* __restrict__ b_ih, const float* __restrict__ b_hh,
    const float* __restrict__ W_ihr, const float* __restrict__ W_hhr,
    const float* __restrict__ b_ihr, const float* __restrict__ b_hhr,
    const float* __restrict__ fcW, const float* __restrict__ fc_b,
    float* __restrict__ out) {
    __shared__ __align__(16) char sraw[SRAW_BYTES];
    GemmBufs& g = *(GemmBufs*)sraw;
    float (*zs)[64] = (float(*)[64])sraw;
    const int bid = blockIdx.x;

    init_phase(bid, yy, h_t, h_tr, c0, c0r);
    pcomp_phase(g, bid, emb, W_ih, W_ihr);
    gbar();

    for (int t = 0; t < TSTEPS; ++t) {
        const int p = t & 1;
        for (int layer = 0; layer < 2; ++layer) {
            cell_phase(g, zs, layer, p, bid, W_ih, W_hh, b_ih, b_hh,
                       W_ihr, W_hhr, b_ihr, b_hhr);
            gbar();
        }
        fc_phase(g, bid, fcW);
        gbar();
        final_phase((float*)sraw, bid, fc_b, out, t);
        gbar();
    }
}

// ---------------- launch: exactly ONE graph node -----------------------------
extern "C" void kernel_launch(void* const* d_in, const int* in_sizes, int n_in,
                              void* d_out, int out_size) {
    const int* yy = (const int*)d_in[0];
    const float* h_t = (const float*)d_in[1];
    const float* h_tr = (const float*)d_in[2];
    // d_in[3] = x_lens (unused by the reference computation)
    const float* emb = (const float*)d_in[4];
    const float* W_ih = (const float*)d_in[5];
    const float* W_hh = (const float*)d_in[6];
    const float* b_ih = (const float*)d_in[7];
    const float* b_hh = (const float*)d_in[8];
    const float* W_ihr = (const float*)d_in[9];
    const float* W_hhr = (const float*)d_in[10];
    const float* b_ihr = (const float*)d_in[11];
    const float* b_hhr = (const float*)d_in[12];
    const float* c0 = (const float*)d_in[13];
    const float* c0r = (const float*)d_in[14];
    const float* fc_W = (const float*)d_in[15];
    const float* fc_b = (const float*)d_in[16];
    float* out = (float*)d_out;

    main_kernel<<<NBLK, 256>>>(yy, h_t, h_tr, c0, c0r, emb,
                               W_ih, W_hh, b_ih, b_hh,
                               W_ihr, W_hhr, b_ihr, b_hhr,
                               fc_W, fc_b, out);
}

// round 11
// speedup vs baseline: 1.4303x; 1.4268x over previous
#include <cuda_runtime.h>
#include <cuda_bf16.h>
#include <math.h>

typedef unsigned long long ull;
typedef unsigned int uint;

#define BATCH  128
#define TSTEPS 256
#define NBLK   128

#define CELL_SLOTS 6291456u            // 384 tiles * 16384 uint4 slots
#define FC_SLOTS   524288u             // 128 tiles * 4096
#define TOT_SLOTS  (CELL_SLOTS + FC_SLOTS)

// dynamic smem map (bytes):
// [0, 73728): two A buffers, each = hi plane 4608 uints + lo plane 4608 uints
// [73728, 107520): zs[128][66] floats (also final-phase scratch)
#define PL_U    4608                   // 128*36 uints per plane
#define ABUF_U  9216                   // uints per buffer (hi+lo)
#define ZS_BYTE 73728
#define SMEM_BYTES 107520

// ---------------- device scratch -------------------------------------------
__device__ float g_P[2][1024][4096];           // emb @ W_ih(l0)^T, fp32
__device__ uint  g_hx[2][2][2][BATCH * 1024];  // packed (hi,lo) bf16 h
__device__ float g_c[2][2][BATCH * 1024];
__device__ uint  g_whx[BATCH * 2048];          // packed scrambled fc input
__device__ float g_logitsP[8][BATCH * 1024];   // split-K partials
__device__ int   g_feed[BATCH];
__device__ int   g_ended[BATCH];
__device__ unsigned g_cnt = 0, g_gen = 0;
__device__ uint4 g_WB[TOT_SLOTS];              // pre-fragmented split-bf16 weights (104MB)

// ---------------- helpers ----------------------------------------------------
__device__ __forceinline__ uint prmt(uint a, uint b, uint s) {
    uint r; asm("prmt.b32 %0, %1, %2, %3;" : "=r"(r) : "r"(a), "r"(b), "r"(s));
    return r;
}
__device__ __forceinline__ uint b2u(__nv_bfloat162 v) { return *reinterpret_cast<uint*>(&v); }
__device__ __forceinline__ uint pack_split(float v) {
    __nv_bfloat16 h = __float2bfloat16_rn(v);
    float hf = __bfloat162float(h);
    __nv_bfloat16 l = __float2bfloat16_rn(v - hf);
    return (uint)__bfloat16_as_ushort(h) | ((uint)__bfloat16_as_ushort(l) << 16);
}
__device__ __forceinline__ float sigf(float x) { return 1.0f / (1.0f + expf(-x)); }

#define MMA_OP(d, a, bb0, bb1) \
    asm volatile( \
        "mma.sync.aligned.m16n8k16.row.col.f32.bf16.bf16.f32 " \
        "{%0,%1,%2,%3}, {%4,%5,%6,%7}, {%8,%9}, {%0,%1,%2,%3};" \
        : "+f"((d)[0]), "+f"((d)[1]), "+f"((d)[2]), "+f"((d)[3]) \
        : "r"((a)[0]), "r"((a)[1]), "r"((a)[2]), "r"((a)[3]), "r"(bb0), "r"(bb1))

// ---------------- f32x2 helpers (pcomp only) --------------------------------
__device__ __forceinline__ ull pk2(float lo, float hi) {
    ull r; asm("mov.b64 %0, {%1,%2};" : "=l"(r) : "f"(lo), "f"(hi)); return r;
}
__device__ __forceinline__ void fma2(ull& d, ull a, ull b) {
    asm("fma.rn.f32x2 %0, %1, %2, %0;" : "+l"(d) : "l"(a), "l"(b));
}
__device__ __forceinline__ float2 unpk(ull v) {
    float2 r; asm("mov.b64 {%0,%1}, %2;" : "=f"(r.x), "=f"(r.y) : "l"(v)); return r;
}

// ---------------- software grid barrier --------------------------------------
__device__ __forceinline__ void gbar() {
    __threadfence();
    __syncthreads();
    if (threadIdx.x == 0) {
        unsigned gen = atomicAdd(&g_gen, 0u);
        unsigned arrived = atomicAdd(&g_cnt, 1u);
        if (arrived == NBLK - 1u) {
            atomicExch(&g_cnt, 0u);
            __threadfence();
            atomicAdd(&g_gen, 1u);
        } else {
            while (atomicAdd(&g_gen, 0u) == gen) { __nanosleep(64); }
        }
        __threadfence();
    }
    __syncthreads();
}

// ---------------- init --------------------------------------------------------
__device__ __forceinline__ void init_phase(int bid, const int* __restrict__ yy,
                                           const float* __restrict__ h_t,
                                           const float* __restrict__ h_tr,
                                           const float* __restrict__ c0,
                                           const float* __restrict__ c0r) {
    const int tid = threadIdx.x;
    const int LBH = BATCH * 1024;
    for (int i = bid * 256 + tid; i < 2 * LBH; i += NBLK * 256) {
        int l = i / LBH, r = i % LBH, j = r & 1023;
        g_hx[l][0][0][r] = pack_split(h_t[l * LBH + r]);
        g_hx[l][1][0][r] = pack_split(h_tr[l * LBH + r]);
        g_c[l][0][r] = c0[l * 1024 + j];
        g_c[l][1][r] = c0r[l * 1024 + j];
    }
    if (bid == 0 && tid < BATCH) {
        g_feed[tid] = yy[tid * TSTEPS];
        g_ended[tid] = 0;
    }
}

// ---------------- setup: split + pre-fragment weights ------------------------
// Cell tile t = (dir*3+seg)*64 + jt : 64n x 1024k, slot = ks*256 + nf*32 + lane.
// fc tile f = et*8 + ks2 : 64n x 256k, slot = ks*256 + nf*32 + lane.
// Fragment (mma m16n8k16 B): lane holds W[row(n)][kb+{0,1}] and [kb+{8,9}],
// n = nf*8 + lane/4, kb = ks*16 + (lane%4)*2.
__device__ void setup_weights(int bid,
    const float* __restrict__ W_ih, const float* __restrict__ W_hh,
    const float* __restrict__ W_ihr, const float* __restrict__ W_hhr,
    const float* __restrict__ fcW) {
    for (uint s = bid * 256 + threadIdx.x; s < TOT_SLOTS; s += NBLK * 256) {
        const float* p;
        if (s < CELL_SLOTS) {
            uint tile = s >> 14, rem = s & 16383u;
            uint ks = rem >> 8, nf = (rem >> 5) & 7, lane = rem & 31;
            uint dir = tile / 192, seg = (tile / 64) % 3, jt = tile & 63;
            const float* W;
            if (seg == 0)      W = dir ? W_hhr : W_hh;
            else if (seg == 1) W = (dir ? W_ihr : W_ih) + (size_t)4096 * 1024;
            else               W = (dir ? W_hhr : W_hh) + (size_t)4096 * 1024;
            uint n = nf * 8 + (lane >> 2);
            uint row = (n >> 4) * 1024 + jt * 16 + (n & 15);
            uint kb = ks * 16 + (lane & 3) * 2;
            p = W + (size_t)row * 1024 + kb;
        } else {
            uint srel = s - CELL_SLOTS;
            uint f = srel >> 12, rem = srel & 4095u;
            uint ks = rem >> 8, nf = (rem >> 5) & 7, lane = rem & 31;
            uint et = f >> 3, ks2 = f & 7;
            uint n = nf * 8 + (lane >> 2);
            uint row = et * 64 + n;
            uint kb = ks2 * 256 + ks * 16 + (lane & 3) * 2;
            p = fcW + (size_t)row * 2048 + kb;
        }
        float2 r01 = __ldg((const float2*)p);
        float2 r89 = __ldg((const float2*)(p + 8));
        __nv_bfloat162 H01 = __floats2bfloat162_rn(r01.x, r01.y);
        __nv_bfloat162 H89 = __floats2bfloat162_rn(r89.x, r89.y);
        __nv_bfloat162 L01 = __floats2bfloat162_rn(r01.x - __bfloat162float(H01.x),
                                                   r01.y - __bfloat162float(H01.y));
        __nv_bfloat162 L89 = __floats2bfloat162_rn(r89.x - __bfloat162float(H89.x),
                                                   r89.y - __bfloat162float(H89.y));
        g_WB[s] = make_uint4(b2u(H01), b2u(H89), b2u(L01), b2u(L89));
    }
}

// ---------------- pcomp (fp32 f32x2): P = emb @ W_ih(l0)^T -------------------
__device__ void pcomp_phase(char* dsm, int bid, const float* __restrict__ emb,
                            const float* __restrict__ W_ih,
                            const float* __restrict__ W_ihr) {
    float (*As)[16][132] = (float(*)[16][132])(dsm);
    float (*Bs)[16][68]  = (float(*)[16][68])(dsm + 2 * 16 * 132 * 4);
    const int tid = threadIdx.x;
    const int ty = tid >> 4, tx = tid & 15;
    const int m0 = ty << 3, n0 = tx << 2;
    const int r = tid >> 2, q4 = (tid & 3) << 2;

    for (int it = 0; it < 8; ++it) {
        int tile = bid + (it << 7);
        int dir = tile >> 9, mt = (tile >> 6) & 7, nt = tile & 63;
        const float* Bw = dir ? W_ihr : W_ih;
        const int m0g = mt << 7, n0g = nt << 6;
        const float* arow0 = emb + (size_t)(m0g + r) * 1024 + q4;
        const float* arow1 = emb + (size_t)(m0g + r + 64) * 1024 + q4;
        const float* brow  = Bw + (size_t)(n0g + r) * 1024 + q4;

        ull acc[4][4];
#pragma unroll
        for (int i = 0; i < 4; i++)
#pragma unroll
            for (int j = 0; j < 4; j++) acc[i][j] = 0ULL;

        float4 pa0 = __ldg((const float4*)arow0);
        float4 pa1 = __ldg((const float4*)arow1);
        float4 pb  = __ldg((const float4*)brow);
        int cur = 0;
        {
            float (*A)[132] = As[0]; float (*B)[68] = Bs[0];
            A[q4+0][r]=pa0.x; A[q4+1][r]=pa0.y; A[q4+2][r]=pa0.z; A[q4+3][r]=pa0.w;
            A[q4+0][r+64]=pa1.x; A[q4+1][r+64]=pa1.y; A[q4+2][r+64]=pa1.z; A[q4+3][r+64]=pa1.w;
            B[q4+0][r]=pb.x; B[q4+1][r]=pb.y; B[q4+2][r]=pb.z; B[q4+3][r]=pb.w;
        }
        __syncthreads();
        for (int kk = 0; kk < 64; ++kk) {
            const bool more = (kk + 1) < 64;
            if (more) {
                int k0 = (kk + 1) << 4;
                pa0 = __ldg((const float4*)(arow0 + k0));
                pa1 = __ldg((const float4*)(arow1 + k0));
                pb  = __ldg((const float4*)(brow + k0));
            }
            {
                const float (*A)[132] = As[cur]; const float (*B)[68] = Bs[cur];
#pragma unroll
                for (int k = 0; k < 16; k++) {
                    const ull* ap = (const ull*)&A[k][m0];
                    ull a0=ap[0], a1=ap[1], a2=ap[2], a3=ap[3];
                    float4 bv = *(const float4*)&B[k][n0];
                    ull p0=pk2(bv.x,bv.x), p1=pk2(bv.y,bv.y), p2=pk2(bv.z,bv.z), p3=pk2(bv.w,bv.w);
                    fma2(acc[0][0],a0,p0); fma2(acc[0][1],a0,p1); fma2(acc[0][2],a0,p2); fma2(acc[0][3],a0,p3);
                    fma2(acc[1][0],a1,p0); fma2(acc[1][1],a1,p1); fma2(acc[1][2],a1,p2); fma2(acc[1][3],a1,p3);
                    fma2(acc[2][0],a2,p0); fma2(acc[2][1],a2,p1); fma2(acc[2][2],a2,p2); fma2(acc[2][3],a2,p3);
                    fma2(acc[3][0],a3,p0); fma2(acc[3][1],a3,p1); fma2(acc[3][2],a3,p2); fma2(acc[3][3],a3,p3);
                }
            }
            if (more) {
                float (*A)[132] = As[cur^1]; float (*B)[68] = Bs[cur^1];
                A[q4+0][r]=pa0.x; A[q4+1][r]=pa0.y; A[q4+2][r]=pa0.z; A[q4+3][r]=pa0.w;
                A[q4+0][r+64]=pa1.x; A[q4+1][r+64]=pa1.y; A[q4+2][r+64]=pa1.z; A[q4+3][r+64]=pa1.w;
                B[q4+0][r]=pb.x; B[q4+1][r]=pb.y; B[q4+2][r]=pb.z; B[q4+3][r]=pb.w;
                __syncthreads();
                cur ^= 1;
            }
        }
        __syncthreads();
#pragma unroll
        for (int mp = 0; mp < 4; mp++) {
            int m = m0g + m0 + (mp << 1);
#pragma unroll
            for (int j = 0; j < 4; j++) {
                float2 v = unpk(acc[mp][j]);
                g_P[dir][m][n0g + n0 + j] = v.x;
                g_P[dir][m + 1][n0g + n0 + j] = v.y;
            }
        }
        __syncthreads();
    }
}

// ---------------- HMMA GEMM core ---------------------------------------------
// zs[128][66] = A[128,K] @ W^T tile (64 n), K = nch*64, A packed (hi,lo) uints.
// Warp layout: wm = wid&3 (32 m), wn = wid>>2 (32 n); 3-product bf16 split.
__device__ __noinline__ void gemm_mma(uint* smA, float (*zs)[66],
    const uint* __restrict__ Ax0, const uint* __restrict__ Ax1,
    int astride, int koff, int nch, int nch0,
    const uint4* __restrict__ tb0, const uint4* __restrict__ tb1) {
    const int tid = threadIdx.x;
    const int lane = tid & 31, wid = tid >> 5;
    const int wm = wid & 3, wn = wid >> 2;
    const int lq = lane >> 2, lr = lane & 3;
    const int cm = tid >> 1, chalf = tid & 1;

    float acc[2][4][4];
#pragma unroll
    for (int i = 0; i < 2; i++)
#pragma unroll
        for (int j = 0; j < 4; j++)
#pragma unroll
            for (int k = 0; k < 4; k++) acc[i][j][k] = 0.0f;

    // stage chunk 0
    {
        const uint* s = Ax0 + (size_t)cm * astride + koff + chalf * 32;
        uint* dh = smA + cm * 36 + chalf * 16;
        uint* dl = dh + PL_U;
#pragma unroll
        for (int i = 0; i < 8; i++) {
            uint4 v = __ldcg((const uint4*)(s + i * 4));
            *(uint2*)(dh + i * 2) = make_uint2(prmt(v.x, v.y, 0x5410), prmt(v.z, v.w, 0x5410));
            *(uint2*)(dl + i * 2) = make_uint2(prmt(v.x, v.y, 0x7632), prmt(v.z, v.w, 0x7632));
        }
    }
    __syncthreads();

    for (int c = 0; c < nch; ++c) {
        const int bi = c & 1;
        const bool more = (c + 1) < nch;
        uint4 pf[8];
        if (more) {
            int cn = c + 1;
            int sg = (cn >= nch0);
            const uint* s = (sg ? Ax1 : Ax0) + (size_t)cm * astride + koff
                            + (cn - (sg ? nch0 : 0)) * 64 + chalf * 32;
#pragma unroll
            for (int i = 0; i < 8; i++) pf[i] = __ldcg((const uint4*)(s + i * 4));
        }
        const uint* Ah = smA + bi * ABUF_U;
        const uint* Al = Ah + PL_U;
        const int sg = (c >= nch0);
        const uint4* tb = sg ? tb1 : tb0;
        const int ksb = (c - (sg ? nch0 : 0)) * 4;
#pragma unroll
        for (int kl = 0; kl < 4; kl++) {
            const uint4* bp = tb + ((size_t)(ksb + kl) * 8 + wn * 4) * 32 + lane;
            uint4 B0 = __ldg(bp);
            uint4 B1 = __ldg(bp + 32);
            uint4 B2 = __ldg(bp + 64);
            uint4 B3 = __ldg(bp + 96);
            const int colh = kl * 8 + lr;
            uint ah[2][4], al[2][4];
#pragma unroll
            for (int mf = 0; mf < 2; mf++) {
                int m = wm * 32 + mf * 16 + lq;
                ah[mf][0] = Ah[m * 36 + colh];       ah[mf][1] = Ah[(m + 8) * 36 + colh];
                ah[mf][2] = Ah[m * 36 + colh + 4];   ah[mf][3] = Ah[(m + 8) * 36 + colh + 4];
                al[mf][0] = Al[m * 36 + colh];       al[mf][1] = Al[(m + 8) * 36 + colh];
                al[mf][2] = Al[m * 36 + colh + 4];   al[mf][3] = Al[(m + 8) * 36 + colh + 4];
            }
#pragma unroll
            for (int mf = 0; mf < 2; mf++) {
                MMA_OP(acc[mf][0], ah[mf], B0.x, B0.y);
                MMA_OP(acc[mf][0], ah[mf], B0.z, B0.w);
                MMA_OP(acc[mf][0], al[mf], B0.x, B0.y);
                MMA_OP(acc[mf][1], ah[mf], B1.x, B1.y);
                MMA_OP(acc[mf][1], ah[mf], B1.z, B1.w);
                MMA_OP(acc[mf][1], al[mf], B1.x, B1.y);
                MMA_OP(acc[mf][2], ah[mf], B2.x, B2.y);
                MMA_OP(acc[mf][2], ah[mf], B2.z, B2.w);
                MMA_OP(acc[mf][2], al[mf], B2.x, B2.y);
                MMA_OP(acc[mf][3], ah[mf], B3.x, B3.y);
                MMA_OP(acc[mf][3], ah[mf], B3.z, B3.w);
                MMA_OP(acc[mf][3], al[mf], B3.x, B3.y);
            }
        }
        if (more) {
            uint* dh = smA + (bi ^ 1) * ABUF_U + cm * 36 + chalf * 16;
            uint* dl = dh + PL_U;
#pragma unroll
            for (int i = 0; i < 8; i++) {
                *(uint2*)(dh + i * 2) = make_uint2(prmt(pf[i].x, pf[i].y, 0x5410),
                                                   prmt(pf[i].z, pf[i].w, 0x5410));
                *(uint2*)(dl + i * 2) = make_uint2(prmt(pf[i].x, pf[i].y, 0x7632),
                                                   prmt(pf[i].z, pf[i].w, 0x7632));
            }
            __syncthreads();
        }
    }
    // accumulators -> zs
#pragma unroll
    for (int mf = 0; mf < 2; mf++) {
#pragma unroll
        for (int f = 0; f < 4; f++) {
            int m = wm * 32 + mf * 16 + lq;
            int n = wn * 32 + f * 8 + lr * 2;
            *(float2*)&zs[m][n]     = make_float2(acc[mf][f][0], acc[mf][f][1]);
            *(float2*)&zs[m + 8][n] = make_float2(acc[mf][f][2], acc[mf][f][3]);
        }
    }
    __syncthreads();
}

// ---------------- epilogues ---------------------------------------------------
__device__ __forceinline__ void cell_epilogue(float (*zs)[66], int layer, int dir,
    int j0, int np, const float* __restrict__ bi, const float* __restrict__ bh) {
    const int tid = threadIdx.x;
#pragma unroll
    for (int it = 0; it < 8; ++it) {
        int pidx = tid + (it << 8);
        int b = pidx >> 4, jj = pidx & 15;
        int jg = j0 + jj;
        float zi = zs[b][jj]      + bi[jg]        + bh[jg];
        float zf = zs[b][16 + jj] + bi[1024 + jg] + bh[1024 + jg];
        float zg = zs[b][32 + jj] + bi[2048 + jg] + bh[2048 + jg];
        float zo = zs[b][48 + jj] + bi[3072 + jg] + bh[3072 + jg];
        if (layer == 0) {
            int feed = __ldcg(&g_feed[b]);
            const float* pr = &g_P[dir][feed][0];
            zi += pr[jg]; zf += pr[1024 + jg]; zg += pr[2048 + jg]; zo += pr[3072 + jg];
        }
        float ig = sigf(zi), fg = sigf(zf), gv = tanhf(zg), og = sigf(zo);
        int idx = b * 1024 + jg;
        float cnew = fg * g_c[layer][dir][idx] + ig * gv;
        float hnew = og * tanhf(cnew);
        g_c[layer][dir][idx] = cnew;
        uint hp = pack_split(hnew);
        g_hx[layer][dir][np][idx] = hp;
        if (layer == 1) {
            int cc = (dir << 10) + jg;  // wh[cc>>4][(cc&15)*128 + b]
            g_whx[((cc >> 4) << 11) + ((cc & 15) << 7) + b] = hp;
        }
    }
}

__device__ __forceinline__ void fc_epilogue(float (*zs)[66], int et, int ks2) {
    const int tid = threadIdx.x;
    const int b = tid >> 1, n0 = (tid & 1) << 5;
    float* lp = &g_logitsP[ks2][b * 1024 + et * 64 + n0];
#pragma unroll
    for (int j = 0; j < 32; j++) lp[j] = zs[b][n0 + j];
}

// ---------------- final phase --------------------------------------------------
__device__ __forceinline__ void final_phase(char* dsm, int bid,
                                            const float* __restrict__ fc_b,
                                            float* __restrict__ out, int t) {
    const int b = bid;
    const int tid = threadIdx.x;
    float* sl = (float*)(dsm + ZS_BYTE);
    float* sv = sl + 1024;
    int*   si = (int*)(sl + 1280);
    float* ssum = sl + 1536;

    const int end = __ldcg(&g_ended[b]);
    float bv = -3.402823466e38f;
    int bidx = 0;
    for (int e = tid; e < 1024; e += 256) {
        float v;
        if (end) {
            v = (e == 1) ? 1.0f : 0.0f;
        } else {
            v = fc_b[e];
#pragma unroll
            for (int s = 0; s < 8; s++) v += __ldcg(&g_logitsP[s][b * 1024 + e]);
        }
        sl[e] = v;
        if (v > bv) { bv = v; bidx = e; }
    }
    sv[tid] = bv; si[tid] = bidx;
    __syncthreads();
    for (int s = 128; s > 0; s >>= 1) {
        if (tid < s) {
            float v2 = sv[tid + s]; int i2 = si[tid + s];
            if (v2 > sv[tid] || (v2 == sv[tid] && i2 < si[tid])) { sv[tid] = v2; si[tid] = i2; }
        }
        __syncthreads();
    }
    float mx = sv[0];
    int label = si[0];
    __syncthreads();

    float ps = 0.0f;
    for (int e = tid; e < 1024; e += 256) ps += expf(sl[e] - mx);
    ssum[tid] = ps;
    __syncthreads();
    for (int s = 128; s > 0; s >>= 1) {
        if (tid < s) ssum[tid] += ssum[tid + s];
        __syncthreads();
    }
    float inv = 1.0f / ssum[0];

    float* orow = out + ((size_t)b * TSTEPS + t) * 1024;
    for (int e = tid; e < 1024; e += 256) orow[e] = expf(sl[e] - mx) * inv;

    if (tid == 0) {
        g_feed[b] = label;
        g_ended[b] = end | (label == 1);  // EOS = 1
    }
}

// ---------------- mega kernel --------------------------------------------------
__global__ void __launch_bounds__(256, 1) main_kernel(
    const int* __restrict__ yy,
    const float* __restrict__ h_t, const float* __restrict__ h_tr,
    const float* __restrict__ c0, const float* __restrict__ c0r,
    const float* __restrict__ emb,
    const float* __restrict__ W_ih, const float* __restrict__ W_hh,
    const float* __restrict__ b_ih, const float* __restrict__ b_hh,
    const float* __restrict__ W_ihr, const float* __restrict__ W_hhr,
    const float* __restrict__ b_ihr, const float* __restrict__ b_hhr,
    const float* __restrict__ fcW, const float* __restrict__ fc_b,
    float* __restrict__ out) {
    extern __shared__ char dsm[];
    uint* smA = (uint*)dsm;
    float (*zs)[66] = (float(*)[66])(dsm + ZS_BYTE);
    const int bid = blockIdx.x;

    init_phase(bid, yy, h_t, h_tr, c0, c0r);
    setup_weights(bid, W_ih, W_hh, W_ihr, W_hhr, fcW);
    pcomp_phase(dsm, bid, emb, W_ih, W_ihr);
    gbar();

    const int dir = bid >> 6;
    const int jt = bid & 63;
    const int j0 = jt << 4;
    const int et = bid >> 3;
    const int ks2 = bid & 7;
    const float* bi0 = (dir ? b_ihr : b_ih);
    const float* bh0 = (dir ? b_hhr : b_hh);
    const float* bi1 = bi0 + 4096;
    const float* bh1 = bh0 + 4096;
    const uint4* tL0  = g_WB + (size_t)((dir * 3 + 0) * 64 + jt) * 16384;
    const uint4* tL1a = g_WB + (size_t)((dir * 3 + 1) * 64 + jt) * 16384;
    const uint4* tL1b = g_WB + (size_t)((dir * 3 + 2) * 64 + jt) * 16384;
    const uint4* tFC  = g_WB + CELL_SLOTS + (size_t)(et * 8 + ks2) * 4096;

    for (int t = 0; t < TSTEPS; ++t) {
        const int p = t & 1;
        const int np = p ^ 1;
        // layer 0: z = h0_prev @ Whh0^T (+ P[feed] in epilogue)
        gemm_mma(smA, zs, g_hx[0][dir][p], g_hx[0][dir][p], 1024, 0, 16, 16, tL0, tL0);
        cell_epilogue(zs, 0, dir, j0, np, bi0, bh0);
        gbar();
        // layer 1: z = h0_new @ Wih1^T + h1_prev @ Whh1^T
        gemm_mma(smA, zs, g_hx[0][dir][np], g_hx[1][dir][p], 1024, 0, 32, 16, tL1a, tL1b);
        cell_epilogue(zs, 1, dir, j0, np, bi1, bh1);
        gbar();
        // fc: logits partial, K slice ks2*256..+256
        gemm_mma(smA, zs, g_whx, g_whx, 2048, ks2 * 256, 4, 4, tFC, tFC);
        fc_epilogue(zs, et, ks2);
        gbar();
        final_phase(dsm, bid, fc_b, out, t);
        gbar();
    }
}

// ---------------- launch --------------------------------------------------------
extern "C" void kernel_launch(void* const* d_in, const int* in_sizes, int n_in,
                              void* d_out, int out_size) {
    const int* yy = (const int*)d_in[0];
    const float* h_t = (const float*)d_in[1];
    const float* h_tr = (const float*)d_in[2];
    // d_in[3] = x_lens (unused by the reference computation)
    const float* emb = (const float*)d_in[4];
    const float* W_ih = (const float*)d_in[5];
    const float* W_hh = (const float*)d_in[6];
    const float* b_ih = (const float*)d_in[7];
    const float* b_hh = (const float*)d_in[8];
    const float* W_ihr = (const float*)d_in[9];
    const float* W_hhr = (const float*)d_in[10];
    const float* b_ihr = (const float*)d_in[11];
    const float* b_hhr = (const float*)d_in[12];
    const float* c0 = (const float*)d_in[13];
    const float* c0r = (const float*)d_in[14];
    const float* fc_W = (const float*)d_in[15];
    const float* fc_b = (const float*)d_in[16];
    float* out = (float*)d_out;

    cudaFuncSetAttribute(main_kernel, cudaFuncAttributeMaxDynamicSharedMemorySize, SMEM_BYTES);
    main_kernel<<<NBLK, 256, SMEM_BYTES>>>(yy, h_t, h_tr, c0, c0r, emb,
                                           W_ih, W_hh, b_ih, b_hh,
                                           W_ihr, W_hhr, b_ihr, b_hhr,
                                           fc_W, fc_b, out);
}

// round 12
// speedup vs baseline: 1.9903x; 1.3916x over previous
#include <cuda_runtime.h>
#include <cuda_bf16.h>
#include <math.h>

typedef unsigned long long ull;
typedef unsigned int uint;

#define BATCH  128
#define TSTEPS 256
#define NBLK   128
#define NTHR   512

#define CELL_SLOTS 6291456u            // 384 tiles * 16384 uint4 slots
#define FC_SLOTS   524288u             // 128 tiles * 4096
#define TOT_SLOTS  (CELL_SLOTS + FC_SLOTS)

// dynamic smem map (bytes):
// [0, 73728)        two A buffers (hi plane 4608 uints + lo plane 4608 uints each)
// [73728, 106496)   two B buffers, 16 KB each (cp.async staged weight chunks)
// [106496, 140288)  zs[128][66] floats (also final-phase scratch)
#define PL_U     4608                  // 128*36 uints per plane
#define ABUF_U   9216                  // uints per A buffer (hi+lo)
#define BSM_OFF  73728
#define ZS_OFF   106496
#define SMEM_BYTES 140288

// ---------------- device scratch -------------------------------------------
__device__ float g_P[2][1024][4096];           // emb @ W_ih(l0)^T, fp32
__device__ uint  g_hx[2][2][2][BATCH * 1024];  // packed (hi,lo) bf16 h
__device__ float g_c[2][2][BATCH * 1024];
__device__ uint  g_whx[BATCH * 2048];          // packed scrambled fc input
__device__ float g_logitsP[8][BATCH * 1024];   // split-K partials
__device__ int   g_feed[BATCH];
__device__ int   g_ended[BATCH];
__device__ unsigned g_cnt = 0, g_gen = 0;
__device__ uint4 g_WB[TOT_SLOTS];              // pre-fragmented split-bf16 weights

// ---------------- helpers ----------------------------------------------------
__device__ __forceinline__ uint prmt(uint a, uint b, uint s) {
    uint r; asm("prmt.b32 %0, %1, %2, %3;" : "=r"(r) : "r"(a), "r"(b), "r"(s));
    return r;
}
__device__ __forceinline__ uint b2u(__nv_bfloat162 v) { return *reinterpret_cast<uint*>(&v); }
__device__ __forceinline__ uint pack_split(float v) {
    __nv_bfloat16 h = __float2bfloat16_rn(v);
    float hf = __bfloat162float(h);
    __nv_bfloat16 l = __float2bfloat16_rn(v - hf);
    return (uint)__bfloat16_as_ushort(h) | ((uint)__bfloat16_as_ushort(l) << 16);
}
__device__ __forceinline__ float sigf(float x) { return 1.0f / (1.0f + expf(-x)); }
__device__ __forceinline__ uint s2u(const void* p) {
    uint a;
    asm("{ .reg .u64 t; cvta.to.shared.u64 t, %1; cvt.u32.u64 %0, t; }" : "=r"(a) : "l"(p));
    return a;
}

#define MMA_OP(d, a, bb0, bb1) \
    asm volatile( \
        "mma.sync.aligned.m16n8k16.row.col.f32.bf16.bf16.f32 " \
        "{%0,%1,%2,%3}, {%4,%5,%6,%7}, {%8,%9}, {%0,%1,%2,%3};" \
        : "+f"((d)[0]), "+f"((d)[1]), "+f"((d)[2]), "+f"((d)[3]) \
        : "r"((a)[0]), "r"((a)[1]), "r"((a)[2]), "r"((a)[3]), "r"(bb0), "r"(bb1))

#define CP_ASYNC16(daddr, saddr) \
    asm volatile("cp.async.cg.shared.global [%0], [%1], 16;" :: "r"(daddr), "l"(saddr) : "memory")
#define CP_COMMIT() asm volatile("cp.async.commit_group;" ::: "memory")
#define CP_WAIT1()  asm volatile("cp.async.wait_group 1;" ::: "memory")
#define CP_WAIT0()  asm volatile("cp.async.wait_group 0;" ::: "memory")

// ---------------- f32x2 helpers (pcomp only) --------------------------------
__device__ __forceinline__ ull pk2(float lo, float hi) {
    ull r; asm("mov.b64 %0, {%1,%2};" : "=l"(r) : "f"(lo), "f"(hi)); return r;
}
__device__ __forceinline__ void fma2(ull& d, ull a, ull b) {
    asm("fma.rn.f32x2 %0, %1, %2, %0;" : "+l"(d) : "l"(a), "l"(b));
}
__device__ __forceinline__ float2 unpk(ull v) {
    float2 r; asm("mov.b64 {%0,%1}, %2;" : "=f"(r.x), "=f"(r.y) : "l"(v)); return r;
}

// ---------------- software grid barrier --------------------------------------
__device__ __forceinline__ void gbar() {
    __threadfence();
    __syncthreads();
    if (threadIdx.x == 0) {
        unsigned gen = atomicAdd(&g_gen, 0u);
        unsigned arrived = atomicAdd(&g_cnt, 1u);
        if (arrived == NBLK - 1u) {
            atomicExch(&g_cnt, 0u);
            __threadfence();
            atomicAdd(&g_gen, 1u);
        } else {
            while (atomicAdd(&g_gen, 0u) == gen) { __nanosleep(64); }
        }
        __threadfence();
    }
    __syncthreads();
}

// ---------------- init --------------------------------------------------------
__device__ __forceinline__ void init_phase(int bid, const int* __restrict__ yy,
                                           const float* __restrict__ h_t,
                                           const float* __restrict__ h_tr,
                                           const float* __restrict__ c0,
                                           const float* __restrict__ c0r) {
    const int tid = threadIdx.x;
    const int LBH = BATCH * 1024;
    for (int i = bid * NTHR + tid; i < 2 * LBH; i += NBLK * NTHR) {
        int l = i / LBH, r = i % LBH, j = r & 1023;
        g_hx[l][0][0][r] = pack_split(h_t[l * LBH + r]);
        g_hx[l][1][0][r] = pack_split(h_tr[l * LBH + r]);
        g_c[l][0][r] = c0[l * 1024 + j];
        g_c[l][1][r] = c0r[l * 1024 + j];
    }
    if (bid == 0 && tid < BATCH) {
        g_feed[tid] = yy[tid * TSTEPS];
        g_ended[tid] = 0;
    }
}

// ---------------- setup: split + pre-fragment weights ------------------------
__device__ void setup_weights(int bid,
    const float* __restrict__ W_ih, const float* __restrict__ W_hh,
    const float* __restrict__ W_ihr, const float* __restrict__ W_hhr,
    const float* __restrict__ fcW) {
    for (uint s = bid * NTHR + threadIdx.x; s < TOT_SLOTS; s += NBLK * NTHR) {
        const float* p;
        if (s < CELL_SLOTS) {
            uint tile = s >> 14, rem = s & 16383u;
            uint ks = rem >> 8, nf = (rem >> 5) & 7, lane = rem & 31;
            uint dir = tile / 192, seg = (tile / 64) % 3, jt = tile & 63;
            const float* W;
            if (seg == 0)      W = dir ? W_hhr : W_hh;
            else if (seg == 1) W = (dir ? W_ihr : W_ih) + (size_t)4096 * 1024;
            else               W = (dir ? W_hhr : W_hh) + (size_t)4096 * 1024;
            uint n = nf * 8 + (lane >> 2);
            uint row = (n >> 4) * 1024 + jt * 16 + (n & 15);
            uint kb = ks * 16 + (lane & 3) * 2;
            p = W + (size_t)row * 1024 + kb;
        } else {
            uint srel = s - CELL_SLOTS;
            uint f = srel >> 12, rem = srel & 4095u;
            uint ks = rem >> 8, nf = (rem >> 5) & 7, lane = rem & 31;
            uint et = f >> 3, ks2 = f & 7;
            uint n = nf * 8 + (lane >> 2);
            uint row = et * 64 + n;
            uint kb = ks2 * 256 + ks * 16 + (lane & 3) * 2;
            p = fcW + (size_t)row * 2048 + kb;
        }
        float2 r01 = __ldg((const float2*)p);
        float2 r89 = __ldg((const float2*)(p + 8));
        __nv_bfloat162 H01 = __floats2bfloat162_rn(r01.x, r01.y);
        __nv_bfloat162 H89 = __floats2bfloat162_rn(r89.x, r89.y);
        __nv_bfloat162 L01 = __floats2bfloat162_rn(r01.x - __bfloat162float(H01.x),
                                                   r01.y - __bfloat162float(H01.y));
        __nv_bfloat162 L89 = __floats2bfloat162_rn(r89.x - __bfloat162float(H89.x),
                                                   r89.y - __bfloat162float(H89.y));
        g_WB[s] = make_uint4(b2u(H01), b2u(H89), b2u(L01), b2u(L89));
    }
}

// ---------------- pcomp (fp32 f32x2, 512 thr): P = emb @ W_ih(l0)^T ----------
__device__ void pcomp_phase(char* dsm, int bid, const float* __restrict__ emb,
                            const float* __restrict__ W_ih,
                            const float* __restrict__ W_ihr) {
    float (*As)[16][132] = (float(*)[16][132])(dsm);
    float (*Bs)[16][68]  = (float(*)[16][68])(dsm + 2 * 16 * 132 * 4);
    const int tid = threadIdx.x;
    const int ty = tid >> 4, tx = tid & 15;
    const int m0 = ty << 2, n0 = tx << 2;
    const int ar = tid >> 2, q4 = (tid & 3) << 2;
    const bool bload = (tid < 256);
    const int br = tid >> 2;   // 0..63 when bload

    for (int it = 0; it < 8; ++it) {
        int tile = bid + (it << 7);
        int dir = tile >> 9, mt = (tile >> 6) & 7, nt = tile & 63;
        const float* Bw = dir ? W_ihr : W_ih;
        const int m0g = mt << 7, n0g = nt << 6;
        const float* arow = emb + (size_t)(m0g + ar) * 1024 + q4;
        const float* brow = Bw + (size_t)(n0g + br) * 1024 + q4;

        ull acc[2][4];
#pragma unroll
        for (int i = 0; i < 2; i++)
#pragma unroll
            for (int j = 0; j < 4; j++) acc[i][j] = 0ULL;

        float4 pa = __ldg((const float4*)arow);
        float4 pb = make_float4(0.f, 0.f, 0.f, 0.f);
        if (bload) pb = __ldg((const float4*)brow);
        int cur = 0;
        {
            float (*A)[132] = As[0]; float (*B)[68] = Bs[0];
            A[q4+0][ar]=pa.x; A[q4+1][ar]=pa.y; A[q4+2][ar]=pa.z; A[q4+3][ar]=pa.w;
            if (bload) { B[q4+0][br]=pb.x; B[q4+1][br]=pb.y; B[q4+2][br]=pb.z; B[q4+3][br]=pb.w; }
        }
        __syncthreads();
        for (int kk = 0; kk < 64; ++kk) {
            const bool more = (kk + 1) < 64;
            if (more) {
                int k0 = (kk + 1) << 4;
                pa = __ldg((const float4*)(arow + k0));
                if (bload) pb = __ldg((const float4*)(brow + k0));
            }
            {
                const float (*A)[132] = As[cur]; const float (*B)[68] = Bs[cur];
#pragma unroll
                for (int k = 0; k < 16; k++) {
                    const ull* ap = (const ull*)&A[k][m0];
                    ull a0 = ap[0], a1 = ap[1];
                    float4 bv = *(const float4*)&B[k][n0];
                    ull p0=pk2(bv.x,bv.x), p1=pk2(bv.y,bv.y), p2=pk2(bv.z,bv.z), p3=pk2(bv.w,bv.w);
                    fma2(acc[0][0],a0,p0); fma2(acc[0][1],a0,p1); fma2(acc[0][2],a0,p2); fma2(acc[0][3],a0,p3);
                    fma2(acc[1][0],a1,p0); fma2(acc[1][1],a1,p1); fma2(acc[1][2],a1,p2); fma2(acc[1][3],a1,p3);
                }
            }
            if (more) {
                float (*A)[132] = As[cur^1]; float (*B)[68] = Bs[cur^1];
                A[q4+0][ar]=pa.x; A[q4+1][ar]=pa.y; A[q4+2][ar]=pa.z; A[q4+3][ar]=pa.w;
                if (bload) { B[q4+0][br]=pb.x; B[q4+1][br]=pb.y; B[q4+2][br]=pb.z; B[q4+3][br]=pb.w; }
                __syncthreads();
                cur ^= 1;
            }
        }
        __syncthreads();
#pragma unroll
        for (int mp = 0; mp < 2; mp++) {
            int m = m0g + m0 + (mp << 1);
#pragma unroll
            for (int j = 0; j < 4; j++) {
                float2 v = unpk(acc[mp][j]);
                g_P[dir][m][n0g + n0 + j] = v.x;
                g_P[dir][m + 1][n0g + n0 + j] = v.y;
            }
        }
        __syncthreads();
    }
}

// ---------------- HMMA GEMM core (512 thr, cp.async weight stream) ----------
// zs[128][66] = A[128, K] @ W^T tile (64 n); A packed (hi,lo) uints;
// warp tile 16m x 32n; B chunks (16 KB) double-buffered in smem via cp.async.
__device__ __noinline__ void gemm_mma(uint* smA, uint smb, float (*zs)[66],
    const uint* __restrict__ Ax0, const uint* __restrict__ Ax1,
    int astride, int koff, int nch, int nch0,
    const uint4* __restrict__ tb0, const uint4* __restrict__ tb1) {
    const int tid = threadIdx.x;
    const int lane = tid & 31, wid = tid >> 5;
    const int wn = wid & 1, wm = wid >> 1;
    const int lq = lane >> 2, lr = lane & 3;
    const int ar = tid >> 2, aq = tid & 3;
    uint4* smB = (uint4*)((char*)smA + BSM_OFF);
    const uint smbB = smb + BSM_OFF;

    float acc[4][4];
#pragma unroll
    for (int f = 0; f < 4; f++)
#pragma unroll
        for (int k = 0; k < 4; k++) acc[f][k] = 0.0f;

    // ---- prologue: B0 (cp.async), A0 (reg->prmt->smem), B1 (cp.async)
    {
        const uint4* s = ((0 >= nch0) ? tb1 : tb0) + tid;
        uint d = smbB + tid * 16;
        CP_ASYNC16(d, s);
        CP_ASYNC16(d + 512 * 16, s + 512);
        CP_COMMIT();
    }
    {
        const uint* s = Ax0 + (size_t)ar * astride + koff + aq * 16;
        uint* dh = smA + ar * 36 + aq * 8;
        uint* dl = dh + PL_U;
#pragma unroll
        for (int i = 0; i < 4; i++) {
            uint4 v = __ldcg((const uint4*)(s + i * 4));
            *(uint2*)(dh + i * 2) = make_uint2(prmt(v.x, v.y, 0x5410), prmt(v.z, v.w, 0x5410));
            *(uint2*)(dl + i * 2) = make_uint2(prmt(v.x, v.y, 0x7632), prmt(v.z, v.w, 0x7632));
        }
    }
    if (nch > 1) {
        int sg = (1 >= nch0);
        const uint4* s = (sg ? tb1 : tb0) + (size_t)(1 - (sg ? nch0 : 0)) * 1024 + tid;
        uint d = smbB + 16384 + tid * 16;
        CP_ASYNC16(d, s);
        CP_ASYNC16(d + 512 * 16, s + 512);
        CP_COMMIT();
        CP_WAIT1();
    } else {
        CP_WAIT0();
    }
    __syncthreads();

    for (int c = 0; c < nch; ++c) {
        const int bi = c & 1;
        const bool more = (c + 1) < nch;
        uint4 av[4];
        if (more) {
            int cn = c + 1;
            int sg = (cn >= nch0);
            const uint* s = (sg ? Ax1 : Ax0) + (size_t)ar * astride + koff
                            + (cn - (sg ? nch0 : 0)) * 64 + aq * 16;
#pragma unroll
            for (int i = 0; i < 4; i++) av[i] = __ldcg((const uint4*)(s + i * 4));
        }
        const uint* Ah = smA + bi * ABUF_U;
        const uint* Al = Ah + PL_U;
        const uint4* Bb = smB + bi * 1024;
#pragma unroll
        for (int kl = 0; kl < 4; kl++) {
            const uint4* bp = Bb + (kl * 8 + wn * 4) * 32 + lane;
            uint4 B0 = bp[0], B1 = bp[32], B2 = bp[64], B3 = bp[96];
            const int colh = kl * 8 + lr;
            const int m = wm * 16 + lq;
            uint ah[4], al[4];
            ah[0] = Ah[m * 36 + colh];     ah[1] = Ah[(m + 8) * 36 + colh];
            ah[2] = Ah[m * 36 + colh + 4]; ah[3] = Ah[(m + 8) * 36 + colh + 4];
            al[0] = Al[m * 36 + colh];     al[1] = Al[(m + 8) * 36 + colh];
            al[2] = Al[m * 36 + colh + 4]; al[3] = Al[(m + 8) * 36 + colh + 4];
            MMA_OP(acc[0], ah, B0.x, B0.y); MMA_OP(acc[0], ah, B0.z, B0.w); MMA_OP(acc[0], al, B0.x, B0.y);
            MMA_OP(acc[1], ah, B1.x, B1.y); MMA_OP(acc[1], ah, B1.z, B1.w); MMA_OP(acc[1], al, B1.x, B1.y);
            MMA_OP(acc[2], ah, B2.x, B2.y); MMA_OP(acc[2], ah, B2.z, B2.w); MMA_OP(acc[2], al, B2.x, B2.y);
            MMA_OP(acc[3], ah, B3.x, B3.y); MMA_OP(acc[3], ah, B3.z, B3.w); MMA_OP(acc[3], al, B3.x, B3.y);
        }
        if (more) {
            // stage A(c+1)
            uint* dh = smA + (bi ^ 1) * ABUF_U + ar * 36 + aq * 8;
            uint* dl = dh + PL_U;
#pragma unroll
            for (int i = 0; i < 4; i++) {
                *(uint2*)(dh + i * 2) = make_uint2(prmt(av[i].x, av[i].y, 0x5410),
                                                   prmt(av[i].z, av[i].w, 0x5410));
                *(uint2*)(dl + i * 2) = make_uint2(prmt(av[i].x, av[i].y, 0x7632),
                                                   prmt(av[i].z, av[i].w, 0x7632));
            }
            // queue B(c+2) into buffer just consumed
            if (c + 2 < nch) {
                int cn = c + 2;
                int sg = (cn >= nch0);
                const uint4* s = (sg ? tb1 : tb0) + (size_t)(cn - (sg ? nch0 : 0)) * 1024 + tid;
                uint d = smbB + bi * 16384 + tid * 16;
                CP_ASYNC16(d, s);
                CP_ASYNC16(d + 512 * 16, s + 512);
                CP_COMMIT();
                CP_WAIT1();
            } else {
                CP_WAIT0();
            }
            __syncthreads();
        }
    }

    // accumulators -> zs
#pragma unroll
    for (int f = 0; f < 4; f++) {
        int m = wm * 16 + lq;
        int n = wn * 32 + f * 8 + lr * 2;
        *(float2*)&zs[m][n]     = make_float2(acc[f][0], acc[f][1]);
        *(float2*)&zs[m + 8][n] = make_float2(acc[f][2], acc[f][3]);
    }
    __syncthreads();
}

// ---------------- epilogues ---------------------------------------------------
__device__ __forceinline__ void cell_epilogue(float (*zs)[66], int layer, int dir,
    int j0, int np, const float* __restrict__ bi, const float* __restrict__ bh) {
    const int tid = threadIdx.x;
#pragma unroll
    for (int it = 0; it < 4; ++it) {
        int pidx = tid + it * NTHR;
        int b = pidx >> 4, jj = pidx & 15;
        int jg = j0 + jj;
        float zi = zs[b][jj]      + bi[jg]        + bh[jg];
        float zf = zs[b][16 + jj] + bi[1024 + jg] + bh[1024 + jg];
        float zg = zs[b][32 + jj] + bi[2048 + jg] + bh[2048 + jg];
        float zo = zs[b][48 + jj] + bi[3072 + jg] + bh[3072 + jg];
        if (layer == 0) {
            int feed = __ldcg(&g_feed[b]);
            const float* pr = &g_P[dir][feed][0];
            zi += pr[jg]; zf += pr[1024 + jg]; zg += pr[2048 + jg]; zo += pr[3072 + jg];
        }
        float ig = sigf(zi), fg = sigf(zf), gv = tanhf(zg), og = sigf(zo);
        int idx = b * 1024 + jg;
        float cnew = fg * g_c[layer][dir][idx] + ig * gv;
        float hnew = og * tanhf(cnew);
        g_c[layer][dir][idx] = cnew;
        uint hp = pack_split(hnew);
        g_hx[layer][dir][np][idx] = hp;
        if (layer == 1) {
            int cc = (dir << 10) + jg;  // wh[cc>>4][(cc&15)*128 + b]
            g_whx[((cc >> 4) << 11) + ((cc & 15) << 7) + b] = hp;
        }
    }
}

__device__ __forceinline__ void fc_epilogue(float (*zs)[66], int et, int ks2) {
    const int tid = threadIdx.x;
    const int b = tid >> 2, n0 = (tid & 3) << 4;
    float* lp = &g_logitsP[ks2][b * 1024 + et * 64 + n0];
#pragma unroll
    for (int j = 0; j < 16; j++) lp[j] = zs[b][n0 + j];
}

// ---------------- final phase --------------------------------------------------
__device__ __forceinline__ void final_phase(char* dsm, int bid,
                                            const float* __restrict__ fc_b,
                                            float* __restrict__ out, int t) {
    const int b = bid;
    const int tid = threadIdx.x;
    float* sl = (float*)(dsm + ZS_OFF);
    float* sv = sl + 1024;
    int*   si = (int*)(sl + 1536);
    float* ssum = sl + 2048;

    const int end = __ldcg(&g_ended[b]);
    float bv = -3.402823466e38f;
    int bidx = 0;
    for (int e = tid; e < 1024; e += NTHR) {
        float v;
        if (end) {
            v = (e == 1) ? 1.0f : 0.0f;
        } else {
            v = fc_b[e];
#pragma unroll
            for (int s = 0; s < 8; s++) v += __ldcg(&g_logitsP[s][b * 1024 + e]);
        }
        sl[e] = v;
        if (v > bv) { bv = v; bidx = e; }
    }
    sv[tid] = bv; si[tid] = bidx;
    __syncthreads();
    for (int s = NTHR / 2; s > 0; s >>= 1) {
        if (tid < s) {
            float v2 = sv[tid + s]; int i2 = si[tid + s];
            if (v2 > sv[tid] || (v2 == sv[tid] && i2 < si[tid])) { sv[tid] = v2; si[tid] = i2; }
        }
        __syncthreads();
    }
    float mx = sv[0];
    int label = si[0];
    __syncthreads();

    float ps = 0.0f;
    for (int e = tid; e < 1024; e += NTHR) ps += expf(sl[e] - mx);
    ssum[tid] = ps;
    __syncthreads();
    for (int s = NTHR / 2; s > 0; s >>= 1) {
        if (tid < s) ssum[tid] += ssum[tid + s];
        __syncthreads();
    }
    float inv = 1.0f / ssum[0];

    float* orow = out + ((size_t)b * TSTEPS + t) * 1024;
    for (int e = tid; e < 1024; e += NTHR) orow[e] = expf(sl[e] - mx) * inv;

    if (tid == 0) {
        g_feed[b] = label;
        g_ended[b] = end | (label == 1);  // EOS = 1
    }
}

// ---------------- mega kernel --------------------------------------------------
__global__ void __launch_bounds__(NTHR, 1) main_kernel(
    const int* __restrict__ yy,
    const float* __restrict__ h_t, const float* __restrict__ h_tr,
    const float* __restrict__ c0, const float* __restrict__ c0r,
    const float* __restrict__ emb,
    const float* __restrict__ W_ih, const float* __restrict__ W_hh,
    const float* __restrict__ b_ih, const float* __restrict__ b_hh,
    const float* __restrict__ W_ihr, const float* __restrict__ W_hhr,
    const float* __restrict__ b_ihr, const float* __restrict__ b_hhr,
    const float* __restrict__ fcW, const float* __restrict__ fc_b,
    float* __restrict__ out) {
    extern __shared__ char dsm[];
    uint* smA = (uint*)dsm;
    const uint smb = s2u(dsm);
    float (*zs)[66] = (float(*)[66])(dsm + ZS_OFF);
    const int bid = blockIdx.x;

    init_phase(bid, yy, h_t, h_tr, c0, c0r);
    setup_weights(bid, W_ih, W_hh, W_ihr, W_hhr, fcW);
    pcomp_phase(dsm, bid, emb, W_ih, W_ihr);
    gbar();

    const int dir = bid >> 6;
    const int jt = bid & 63;
    const int j0 = jt << 4;
    const int et = bid >> 3;
    const int ks2 = bid & 7;
    const float* bi0 = (dir ? b_ihr : b_ih);
    const float* bh0 = (dir ? b_hhr : b_hh);
    const float* bi1 = bi0 + 4096;
    const float* bh1 = bh0 + 4096;
    const uint4* tL0  = g_WB + (size_t)((dir * 3 + 0) * 64 + jt) * 16384;
    const uint4* tL1a = g_WB + (size_t)((dir * 3 + 1) * 64 + jt) * 16384;
    const uint4* tL1b = g_WB + (size_t)((dir * 3 + 2) * 64 + jt) * 16384;
    const uint4* tFC  = g_WB + CELL_SLOTS + (size_t)(et * 8 + ks2) * 4096;

    for (int t = 0; t < TSTEPS; ++t) {
        const int p = t & 1;
        const int np = p ^ 1;
        // layer 0: z = h0_prev @ Whh0^T (+ P[feed] in epilogue)
        gemm_mma(smA, smb, zs, g_hx[0][dir][p], g_hx[0][dir][p], 1024, 0, 16, 16, tL0, tL0);
        cell_epilogue(zs, 0, dir, j0, np, bi0, bh0);
        gbar();
        // layer 1: z = h0_new @ Wih1^T + h1_prev @ Whh1^T
        gemm_mma(smA, smb, zs, g_hx[0][dir][np], g_hx[1][dir][p], 1024, 0, 32, 16, tL1a, tL1b);
        cell_epilogue(zs, 1, dir, j0, np, bi1, bh1);
        gbar();
        // fc: logits partial, K slice ks2*256..+256
        gemm_mma(smA, smb, zs, g_whx, g_whx, 2048, ks2 * 256, 4, 4, tFC, tFC);
        fc_epilogue(zs, et, ks2);
        gbar();
        final_phase(dsm, bid, fc_b, out, t);
        gbar();
    }
}

// ---------------- launch --------------------------------------------------------
extern "C" void kernel_launch(void* const* d_in, const int* in_sizes, int n_in,
                              void* d_out, int out_size) {
    const int* yy = (const int*)d_in[0];
    const float* h_t = (const float*)d_in[1];
    const float* h_tr = (const float*)d_in[2];
    // d_in[3] = x_lens (unused by the reference computation)
    const float* emb = (const float*)d_in[4];
    const float* W_ih = (const float*)d_in[5];
    const float* W_hh = (const float*)d_in[6];
    const float* b_ih = (const float*)d_in[7];
    const float* b_hh = (const float*)d_in[8];
    const float* W_ihr = (const float*)d_in[9];
    const float* W_hhr = (const float*)d_in[10];
    const float* b_ihr = (const float*)d_in[11];
    const float* b_hhr = (const float*)d_in[12];
    const float* c0 = (const float*)d_in[13];
    const float* c0r = (const float*)d_in[14];
    const float* fc_W = (const float*)d_in[15];
    const float* fc_b = (const float*)d_in[16];
    float* out = (float*)d_out;

    cudaFuncSetAttribute(main_kernel, cudaFuncAttributeMaxDynamicSharedMemorySize, SMEM_BYTES);
    main_kernel<<<NBLK, NTHR, SMEM_BYTES>>>(yy, h_t, h_tr, c0, c0r, emb,
                                            W_ih, W_hh, b_ih, b_hh,
                                            W_ihr, W_hhr, b_ihr, b_hhr,
                                            fc_W, fc_b, out);
}